// round 10
// baseline (speedup 1.0000x reference)
#include <cuda_runtime.h>

#define Bn   2
#define Tn   7
#define Hn   128
#define Wn   128
#define Pn   343            // 7*7*7 taps
#define Un   16
#define HW   (Hn*Wn)        // 16384
#define WT   16             // w-tile per block
#define RL   24             // padded patch row length (WT+6=22 -> 24)
#define CSTR (49*RL)        // channel stride in smem (floats)
#define NT   64             // threads per block

// R10: R3's proven inner loop (front-batched float4 LDG x7 taps) with SMALL
// blocks for full-grid residency. Grid 2048, 14 blocks/SM resident (smem
// 14.1KB x14 = 198KB, regs <=73) -> single wave, no trailing tail.
// R3's 134us had 6.92 blocks work/SM but only 6 resident -> ~15% tail idle.
// Block: 64 thr = 16 u x 4 w-groups (float4). Fused softmax-without-max,
// filt (719MB) streamed exactly once with __ldcs.
__global__ __launch_bounds__(NT, 14)
void dynfilt_kernel(const float* __restrict__ x,
                    const float* __restrict__ filt,
                    float* __restrict__ out)
{
    __shared__ float sm[3 * CSTR];   // 14.1 KB

    const int bx    = blockIdx.x;
    const int wq    = bx & 7;            // w eighth
    const int h     = (bx >> 3) & 127;   // row
    const int b     = bx >> 10;          // batch
    const int tid   = threadIdx.x;
    const int u     = tid >> 2;          // 0..15
    const int wg    = tid & 3;           // 0..3 -> w0 = 4*wg
    const int wbase = wq * WT;

    // ---- stage x patches: sm[(c*49 + t*7 + kh)*RL + j], j in [0,22), pad 0 ----
    for (int idx = tid; idx < 3 * 49 * RL; idx += NT) {
        int j   = idx % RL;
        int r   = idx / RL;          // c*49 + row
        int row = r % 49;            // t*7 + kh
        int c   = r / 49;
        int t   = row / 7;
        int kh  = row % 7;
        int gh  = h + kh - 3;
        int gw  = wbase + j - 3;
        float v = 0.f;
        if (j < WT + 6 && (unsigned)gh < (unsigned)Hn && (unsigned)gw < (unsigned)Wn)
            v = x[(((size_t)(b * 3 + c) * Tn + t) * Hn + gh) * Wn + gw];
        sm[idx] = v;
    }
    __syncthreads();

    float acc[3][4] = {{0.f,0.f,0.f,0.f},{0.f,0.f,0.f,0.f},{0.f,0.f,0.f,0.f}};
    float ls[4]     = {0.f, 0.f, 0.f, 0.f};

    // filt[b, p, u, h, w]; per-tap stride = Un*HW elems (1 MB).
    const size_t TAP = (size_t)Un * HW;
    const float* fp = filt + (((size_t)b * Pn) * Un + (size_t)u) * HW
                           + (size_t)h * Wn + wbase + 4 * wg;

    #pragma unroll 1
    for (int r = 0; r < 49; ++r) {
        const float* srow = sm + r * RL + 4 * wg;   // 16B aligned

        // ---- front-batch all 7 tap loads of this row (LDG.128) ----
        float4 f[7];
        #pragma unroll
        for (int i = 0; i < 7; ++i)
            f[i] = __ldcs((const float4*)(fp + (size_t)i * TAP));

        // ---- patch window [0..11] for 3 channels ----
        float pw[3][12];
        #pragma unroll
        for (int c = 0; c < 3; ++c) {
            float4 q0 = *(const float4*)(srow + c * CSTR);
            float4 q1 = *(const float4*)(srow + c * CSTR + 4);
            float4 q2 = *(const float4*)(srow + c * CSTR + 8);
            pw[c][0] = q0.x; pw[c][1]  = q0.y; pw[c][2]  = q0.z; pw[c][3]  = q0.w;
            pw[c][4] = q1.x; pw[c][5]  = q1.y; pw[c][6]  = q1.z; pw[c][7]  = q1.w;
            pw[c][8] = q2.x; pw[c][9]  = q2.y; pw[c][10] = q2.z; pw[c][11] = q2.w;
        }

        // ---- compute: 7 taps x 4 w ----
        #pragma unroll
        for (int kw = 0; kw < 7; ++kw) {
            float e0 = __expf(f[kw].x);
            float e1 = __expf(f[kw].y);
            float e2 = __expf(f[kw].z);
            float e3 = __expf(f[kw].w);
            ls[0] += e0; ls[1] += e1; ls[2] += e2; ls[3] += e3;
            #pragma unroll
            for (int c = 0; c < 3; ++c) {
                acc[c][0] += e0 * pw[c][kw];
                acc[c][1] += e1 * pw[c][kw + 1];
                acc[c][2] += e2 * pw[c][kw + 2];
                acc[c][3] += e3 * pw[c][kw + 3];
            }
        }

        fp += 7 * TAP;
    }

    // ---- epilogue: normalize + pixel shuffle ----
    // u -> (ur=u/4, uc=u%4); thread w's are wbase+4wg+i -> out col 4*w + uc.
    const int ur = u >> 2, uc = u & 3;
    const int Ho = Hn * 4, Wo = Wn * 4;
    const size_t cstride = (size_t)Ho * Wo;
    size_t obase = ((size_t)(b * 3) * Ho + (4 * h + ur)) * Wo
                 + (size_t)4 * (wbase + 4 * wg) + uc;

    #pragma unroll
    for (int i = 0; i < 4; ++i) {
        float inv = 1.f / ls[i];
        out[obase + 4 * i]               = acc[0][i] * inv;
        out[obase + 4 * i + cstride]     = acc[1][i] * inv;
        out[obase + 4 * i + 2 * cstride] = acc[2][i] * inv;
    }
}

extern "C" void kernel_launch(void* const* d_in, const int* in_sizes, int n_in,
                              void* d_out, int out_size)
{
    const float* x    = (const float*)d_in[0];   // [2,3,7,128,128]
    const float* filt = (const float*)d_in[1];   // [2,343,16,128,128]
    float* out        = (float*)d_out;           // [2,3,512,512]

    // Max smem carveout so 14 blocks/SM (198 KB) actually fit.
    static bool configured = false;
    if (!configured) {
        cudaFuncSetAttribute(dynfilt_kernel,
                             cudaFuncAttributePreferredSharedMemoryCarveout, 100);
        configured = true;
    }

    // grid = B * H * (W/WT) = 2*128*8 = 2048 blocks, 64 threads each.
    // 148 SMs x 14 resident = 2072 >= 2048 -> single wave, no tail.
    dynfilt_kernel<<<Bn * Hn * (Wn / WT), NT>>>(x, filt, out);
}